// round 10
// baseline (speedup 1.0000x reference)
#include <cuda_runtime.h>
#include <cuda_bf16.h>
#include <cstdint>

#define SCORE_THRESH 0.2f
#define NMS_THRESH   0.5f
#define MAXH 15
#define MAXO 15
#define KOUT 30
#define NCLS 81
#define G    4            // CTAs per batch
#define NJ   21           // classes per CTA = ceil(81/4)
#define CAP  64           // per-class capacity (mean ~20, 64 ≈ 9.7 sigma)
#define BMAX 64
#define NOBJ (NCLS - 1)   // 80 object classes
#define NOKEYS (NOBJ * MAXO)   // 1200
#define NTHREADS 672

typedef unsigned long long u64;

// Scratch kept-keys per (batch, class); slots zero-padded every run.
__device__ u64 g_keys[BMAX * NCLS * MAXO];
// Arrival counters; never reset — each launch adds exactly G per batch, so
// (old % G == G-1) identifies the last CTA on every launch/replay.
__device__ unsigned int g_done[BMAX];

__device__ __forceinline__ float iou_gt(float ax1, float ay1, float ax2, float ay2,
                                        float bx1, float by1, float bx2, float by2)
{
    float aA = (ax2 - ax1) * (ay2 - ay1);
    float aB = (bx2 - bx1) * (by2 - by1);
    float ltx = fmaxf(ax1, bx1), lty = fmaxf(ay1, by1);
    float rbx = fminf(ax2, bx2), rby = fminf(ay2, by2);
    float iw = fmaxf(rbx - ltx, 0.0f);
    float ih = fmaxf(rby - lty, 0.0f);
    float inter = iw * ih;
    return inter / (aA + aB - inter + 1e-9f);
}

__global__ __launch_bounds__(NTHREADS, 1)
void fused_kernel(const float* __restrict__ boxes,
                  const float* __restrict__ scores,
                  const int*   __restrict__ labels,
                  float* __restrict__ out,
                  int B, int N)
{
    __shared__ u64    bucket[NJ * CAP];     // keys, then sorted keys
    __shared__ float4 sboxes[NJ * CAP];     // sorted candidate boxes
    __shared__ u64    allkeys[NOKEYS];      // merge staging (last CTA only)
    __shared__ int    bcnt[NJ];
    __shared__ int    isLast;

    const int g    = blockIdx.x;            // class group (c % G == g)
    const int b    = blockIdx.y;
    const int tid  = threadIdx.x;
    const int wid  = tid >> 5;
    const int lane = tid & 31;
    const unsigned FULL = 0xFFFFFFFFu;

    const float4* bx4 = (const float4*)(boxes + (size_t)b * N * 4);
    const float4* sc4 = (const float4*)(scores + (size_t)b * N);
    const int4*   lb4 = (const int4*)(labels + (size_t)b * N);

    float* outBoxes  = out;                          // [B][KOUT][4]
    float* outScores = out + (size_t)B * KOUT * 4;
    float* outLabels = out + (size_t)B * KOUT * 5;
    float* outValid  = out + (size_t)B * KOUT * 6;

    if (tid < NJ) bcnt[tid] = 0;
    __syncthreads();

    // ---- Phase A: vectorized scan + scatter keys of our class group ----
    for (int i4 = tid; i4 * 4 < N; i4 += NTHREADS) {
        float4 s = sc4[i4];
        int4   l = lb4[i4];
        int i0 = i4 * 4;
        #pragma unroll
        for (int e = 0; e < 4; e++) {
            float se = (e == 0) ? s.x : (e == 1) ? s.y : (e == 2) ? s.z : s.w;
            int   le = (e == 0) ? l.x : (e == 1) ? l.y : (e == 2) ? l.z : l.w;
            if (se >= SCORE_THRESH && (le & (G - 1)) == g) {
                int j = le >> 2;
                u64 k = ((u64)__float_as_uint(se) << 32) |
                        ((u64)(unsigned)(i0 + e) << 8) | (unsigned)le;
                int p = atomicAdd(&bcnt[j], 1);
                if (p < CAP) bucket[j * CAP + p] = k;
            }
        }
    }
    __syncthreads();

    // ---- Phase B: one class per warp, mask-based NMS ----
    const int  c  = wid * G + g;
    const bool vc = (c < NCLS);
    int cnt = vc ? min(bcnt[wid], CAP) : 0;

    int myKept = -1;                // sorted index kept at round == lane

    if (cnt > 0) {
        const bool use64 = (cnt > 32);
        u64 k0, k1 = 0;

        if (!use64) {
            // 32-element register bitonic sort, descending
            k0 = (lane < cnt) ? bucket[wid * CAP + lane] : 0ull;
            #pragma unroll
            for (int kk = 2; kk <= 32; kk <<= 1) {
                #pragma unroll
                for (int jj = kk >> 1; jj > 0; jj >>= 1) {
                    u64 o = __shfl_xor_sync(FULL, k0, jj);
                    bool lower = (lane & jj) == 0;
                    bool d = (lane & kk) == 0;
                    k0 = (lower == d) ? max(k0, o) : min(k0, o);
                }
            }
        } else {
            // 64-element, 2 keys/lane, descending
            k0 = (lane      < cnt) ? bucket[wid * CAP + lane]      : 0ull;
            k1 = (lane + 32 < cnt) ? bucket[wid * CAP + lane + 32] : 0ull;
            #pragma unroll
            for (int kk = 2; kk <= 64; kk <<= 1) {
                if (kk == 64) { if (k0 < k1) { u64 t = k0; k0 = k1; k1 = t; } }
                #pragma unroll
                for (int jj = (kk == 64) ? 16 : (kk >> 1); jj > 0; jj >>= 1) {
                    bool lower = (lane & jj) == 0;
                    u64 o0 = __shfl_xor_sync(FULL, k0, jj);
                    u64 o1 = __shfl_xor_sync(FULL, k1, jj);
                    bool d0 = ((lane)      & kk) == 0;
                    bool d1 = ((lane + 32) & kk) == 0;
                    k0 = (lower == d0) ? max(k0, o0) : min(k0, o0);
                    k1 = (lower == d1) ? max(k1, o1) : min(k1, o1);
                }
            }
        }

        // fetch boxes of sorted candidates (parallel LDG), stage in smem
        float4 mb0 = make_float4(0, 0, 0, 0), mb1 = make_float4(0, 0, 0, 0);
        if (lane < cnt) mb0 = bx4[(int)((k0 >> 8) & 0xFFFFFFull)];
        if (use64 && lane + 32 < cnt) mb1 = bx4[(int)((k1 >> 8) & 0xFFFFFFull)];
        bucket[wid * CAP + lane] = k0;
        sboxes[wid * CAP + lane] = mb0;
        if (use64) {
            bucket[wid * CAP + lane + 32] = k1;
            sboxes[wid * CAP + lane + 32] = mb1;
        }
        __syncwarp();

        // build suppression masks: bit j set if cand j (rank<mine) IoU>thresh
        unsigned m0 = 0;     // for candidate i = lane      (j < lane < 32)
        u64      m1 = 0;     // for candidate i = lane + 32 (j < 64)
        for (int j = 0; j < cnt; j++) {
            float4 jb = sboxes[wid * CAP + j];   // broadcast LDS
            if (j < lane &&
                iou_gt(mb0.x, mb0.y, mb0.z, mb0.w, jb.x, jb.y, jb.z, jb.w) > NMS_THRESH)
                m0 |= 1u << j;
            if (use64 &&
                iou_gt(mb1.x, mb1.y, mb1.z, mb1.w, jb.x, jb.y, jb.z, jb.w) > NMS_THRESH)
                m1 |= 1ull << j;   // j < lane+32 always (j <= 63, i = lane+32 > j for j < 32+lane; guard below)
        }
        if (use64) m1 &= (lane + 32 < 64) ? ((1ull << (lane + 32)) - 1ull) : ~0ull; // keep only j < i

        // greedy rounds: first alive is kept, its mask column suppresses
        unsigned alive0 = (lane < cnt) ? 1u : 0u;
        unsigned alive1 = (use64 && lane + 32 < cnt) ? 1u : 0u;
        for (int r = 0; r < MAXO; r++) {
            unsigned b0 = __ballot_sync(FULL, alive0);
            unsigned b1 = __ballot_sync(FULL, alive1);
            if (!(b0 | b1)) break;
            int t = b0 ? (__ffs(b0) - 1) : (32 + __ffs(b1) - 1);
            if (lane == r) myKept = t;
            if (t < 32) {
                if (lane == t) alive0 = 0;
                if ((m0 >> t) & 1u)   alive0 = 0;
                if ((m1 >> t) & 1ull) alive1 = 0;
            } else {
                if (lane == t - 32) alive1 = 0;
                if ((m1 >> t) & 1ull) alive1 = 0;
            }
        }
    }

    if (vc) {
        bool v = (myKept >= 0);
        u64 key = v ? bucket[wid * CAP + myKept] : 0ull;
        if (c == 0) {
            if (lane < MAXH) {
                float4 kb = v ? sboxes[wid * CAP + myKept] : make_float4(0, 0, 0, 0);
                float* ob = outBoxes + ((size_t)b * KOUT + lane) * 4;
                *(float4*)ob = kb;
                outScores[b * KOUT + lane] = v ? __uint_as_float((unsigned)(key >> 32)) : 0.0f;
                outLabels[b * KOUT + lane] = v ? 0.0f : -1.0f;
                outValid [b * KOUT + lane] = v ? 1.0f : 0.0f;
            }
        } else {
            if (lane < MAXO)
                g_keys[((size_t)b * NCLS + c) * MAXO + lane] = v ? key : 0ull;
        }
    }

    // ---- last-CTA election (threadFenceReduction pattern) ----
    __syncthreads();
    if (tid == 0) {
        __threadfence();
        unsigned old = atomicAdd(&g_done[b], 1u);
        isLast = ((old & (G - 1)) == (G - 1)) ? 1 : 0;
        if (isLast) __threadfence();
    }
    __syncthreads();
    if (!isLast) return;

    // ---- merge (last CTA): stage 1200 object keys, redux tournament top-15 ----
    const size_t bb = (size_t)b * NCLS * MAXO;
    for (int i = tid; i < NOKEYS; i += NTHREADS) allkeys[i] = g_keys[bb + MAXO + i];
    __syncthreads();

    if (tid < 32) {
        const int l0 = lane, l1 = lane + 32, l2 = lane + 64;
        u64 h0 = allkeys[l0 * MAXO];
        u64 h1 = allkeys[l1 * MAXO];
        u64 h2 = (lane < 16) ? allkeys[l2 * MAXO] : 0ull;
        int p0 = 0, p1 = 0, p2 = 0;

        u64 wkey = 0;
        for (int r = 0; r < MAXO; r++) {
            u64 lmax = max(h0, max(h1, h2));
            unsigned hi = (unsigned)(lmax >> 32);
            unsigned mh = __reduce_max_sync(FULL, hi);
            unsigned lo = (hi == mh) ? (unsigned)lmax : 0u;
            unsigned ml = __reduce_max_sync(FULL, lo);
            u64 win = ((u64)mh << 32) | ml;
            if (win == 0ull) break;
            if (lane == r) wkey = win;
            if (h0 == win)      { p0++; h0 = (p0 < MAXO) ? allkeys[l0 * MAXO + p0] : 0ull; }
            else if (h1 == win) { p1++; h1 = (p1 < MAXO) ? allkeys[l1 * MAXO + p1] : 0ull; }
            else if (h2 == win) { p2++; h2 = (p2 < MAXO) ? allkeys[l2 * MAXO + p2] : 0ull; }
        }

        if (lane < MAXO) {
            int slot = MAXH + lane;
            bool v = (wkey != 0ull);
            float4 wb = v ? bx4[(int)((wkey >> 8) & 0xFFFFFFull)]
                          : make_float4(0, 0, 0, 0);
            float* ob = outBoxes + ((size_t)b * KOUT + slot) * 4;
            *(float4*)ob = wb;
            outScores[b * KOUT + slot] = v ? __uint_as_float((unsigned)(wkey >> 32)) : 0.0f;
            outLabels[b * KOUT + slot] = v ? (float)(int)(wkey & 0xFFull) : -1.0f;
            outValid [b * KOUT + slot] = v ? 1.0f : 0.0f;
        }
    }
}

extern "C" void kernel_launch(void* const* d_in, const int* in_sizes, int n_in,
                              void* d_out, int out_size)
{
    const float* boxes  = (const float*)d_in[0];
    const float* scores = (const float*)d_in[1];
    const int*   labels = (const int*)d_in[2];

    int B = out_size / (KOUT * 7);        // 32
    if (B <= 0) B = 1;
    if (B > BMAX) B = BMAX;
    int N = in_sizes[1] / B;              // 2048

    dim3 grid(G, B);
    fused_kernel<<<grid, NTHREADS>>>(boxes, scores, labels, (float*)d_out, B, N);
}

// round 11
// speedup vs baseline: 1.5607x; 1.5607x over previous
#include <cuda_runtime.h>
#include <cuda_bf16.h>
#include <cstdint>

#define SCORE_THRESH 0.2f
#define NMS_THRESH   0.5f
#define MAXH 15
#define MAXO 15
#define KOUT 30
#define NCLS 81
#define G    4            // CTAs per batch
#define NJ   21           // classes per CTA = ceil(81/4)
#define CAP  64           // per-class capacity (mean ~20, 64 ≈ 9.7 sigma)
#define BMAX 64
#define NOBJ (NCLS - 1)   // 80 object classes
#define NOKEYS (NOBJ * MAXO)   // 1200
#define NTHREADS 672

typedef unsigned long long u64;

// Scratch kept-keys per (batch, class); slots zero-padded every run.
__device__ u64 g_keys[BMAX * NCLS * MAXO];
// Arrival counters; never reset — each launch adds exactly G per batch, so
// (old % G == G-1) identifies the last CTA on every launch/replay.
__device__ unsigned int g_done[BMAX];

__global__ __launch_bounds__(NTHREADS, 1)
void fused_kernel(const float* __restrict__ boxes,
                  const float* __restrict__ scores,
                  const int*   __restrict__ labels,
                  float* __restrict__ out,
                  int B, int N)
{
    __shared__ u64 bucket[NJ * CAP];
    __shared__ u64 allkeys[NOKEYS];     // merge staging (last CTA only)
    __shared__ int bcnt[NJ];
    __shared__ int isLast;

    const int g    = blockIdx.x;        // class group (c % G == g)
    const int b    = blockIdx.y;
    const int tid  = threadIdx.x;
    const int wid  = tid >> 5;
    const int lane = tid & 31;
    const unsigned FULL = 0xFFFFFFFFu;

    const float4* bx4 = (const float4*)(boxes + (size_t)b * N * 4);
    const float4* sc4 = (const float4*)(scores + (size_t)b * N);
    const int4*   lb4 = (const int4*)(labels + (size_t)b * N);

    float* outBoxes  = out;                          // [B][KOUT][4]
    float* outScores = out + (size_t)B * KOUT * 4;
    float* outLabels = out + (size_t)B * KOUT * 5;
    float* outValid  = out + (size_t)B * KOUT * 6;

    if (tid < NJ) bcnt[tid] = 0;
    __syncthreads();

    // ---- Phase A: vectorized scan + scatter keys of our class group ----
    for (int i4 = tid; i4 * 4 < N; i4 += NTHREADS) {
        float4 s = sc4[i4];
        int4   l = lb4[i4];
        int i0 = i4 * 4;
        #pragma unroll
        for (int e = 0; e < 4; e++) {
            float se = (e == 0) ? s.x : (e == 1) ? s.y : (e == 2) ? s.z : s.w;
            int   le = (e == 0) ? l.x : (e == 1) ? l.y : (e == 2) ? l.z : l.w;
            if (se >= SCORE_THRESH && (le & (G - 1)) == g) {
                int j = le >> 2;
                u64 k = ((u64)__float_as_uint(se) << 32) |
                        ((u64)(unsigned)(i0 + e) << 8) | (unsigned)le;
                int p = atomicAdd(&bcnt[j], 1);
                if (p < CAP) bucket[j * CAP + p] = k;
            }
        }
    }
    __syncthreads();

    // ---- Phase B: one class per warp (R9's proven greedy NMS) ----
    const int  c  = wid * G + g;
    const bool vc = (c < NCLS);
    int cnt = vc ? min(bcnt[wid], CAP) : 0;

    float kx1 = 0, ky1 = 0, kx2 = 0, ky2 = 0;   // kept box of rank `lane`
    u64 mykey = 0;
    int kC = 0;

    if (cnt > 0) {
        // 64-element bitonic sort, 2 keys/lane, descending
        u64 k0 = (lane      < cnt) ? bucket[wid * CAP + lane]      : 0ull;
        u64 k1 = (lane + 32 < cnt) ? bucket[wid * CAP + lane + 32] : 0ull;
        #pragma unroll
        for (int kk = 2; kk <= 64; kk <<= 1) {
            if (kk == 64) { if (k0 < k1) { u64 t = k0; k0 = k1; k1 = t; } }
            #pragma unroll
            for (int jj = (kk == 64) ? 16 : (kk >> 1); jj > 0; jj >>= 1) {
                bool lower = (lane & jj) == 0;
                u64 o0 = __shfl_xor_sync(FULL, k0, jj);
                u64 o1 = __shfl_xor_sync(FULL, k1, jj);
                bool d0 = ((lane)      & kk) == 0;
                bool d1 = ((lane + 32) & kk) == 0;
                k0 = (lower == d0) ? max(k0, o0) : min(k0, o0);
                k1 = (lower == d1) ? max(k1, o1) : min(k1, o1);
            }
        }

        // prefetch candidate boxes (parallel LDG)
        float4 mb0 = make_float4(0, 0, 0, 0), mb1 = make_float4(0, 0, 0, 0);
        if (lane      < cnt) mb0 = bx4[(int)((k0 >> 8) & 0xFFFFFFull)];
        if (lane + 32 < cnt) mb1 = bx4[(int)((k1 >> 8) & 0xFFFFFFull)];

        // greedy NMS
        for (int t = 0; t < cnt && kC < MAXO; t++) {
            int sl = t & 31;
            u64   ck  = __shfl_sync(FULL, (t < 32) ? k0    : k1,    sl);
            float cx1 = __shfl_sync(FULL, (t < 32) ? mb0.x : mb1.x, sl);
            float cy1 = __shfl_sync(FULL, (t < 32) ? mb0.y : mb1.y, sl);
            float cx2 = __shfl_sync(FULL, (t < 32) ? mb0.z : mb1.z, sl);
            float cy2 = __shfl_sync(FULL, (t < 32) ? mb0.w : mb1.w, sl);
            float aC  = (cx2 - cx1) * (cy2 - cy1);

            bool sup = false;
            if (lane < kC) {
                float aK  = (kx2 - kx1) * (ky2 - ky1);
                float ltx = fmaxf(cx1, kx1), lty = fmaxf(cy1, ky1);
                float rbx = fminf(cx2, kx2), rby = fminf(cy2, ky2);
                float iw  = fmaxf(rbx - ltx, 0.0f);
                float ih  = fmaxf(rby - lty, 0.0f);
                float inter = iw * ih;
                sup = inter / (aC + aK - inter + 1e-9f) > NMS_THRESH;
            }
            if (!__any_sync(FULL, sup)) {
                if (lane == kC) { kx1 = cx1; ky1 = cy1; kx2 = cx2; ky2 = cy2; mykey = ck; }
                kC++;
            }
        }
    }

    if (vc) {
        if (c == 0) {
            // humans: slots 0..14 (incl. defaults) straight from registers
            if (lane < MAXH) {
                bool v = lane < kC;
                float* ob = outBoxes + ((size_t)b * KOUT + lane) * 4;
                *(float4*)ob = v ? make_float4(kx1, ky1, kx2, ky2)
                                 : make_float4(0, 0, 0, 0);
                outScores[b * KOUT + lane] = v ? __uint_as_float((unsigned)(mykey >> 32)) : 0.0f;
                outLabels[b * KOUT + lane] = v ? 0.0f : -1.0f;
                outValid [b * KOUT + lane] = v ? 1.0f : 0.0f;
            }
        } else {
            u64* dst = g_keys + ((size_t)b * NCLS + c) * MAXO;
            if (lane < MAXO) dst[lane] = (lane < kC) ? mykey : 0ull;
        }
    }

    // ---- last-CTA election (threadFenceReduction pattern) ----
    __syncthreads();
    if (tid == 0) {
        __threadfence();
        unsigned old = atomicAdd(&g_done[b], 1u);
        isLast = ((old & (G - 1)) == (G - 1)) ? 1 : 0;
        if (isLast) __threadfence();
    }
    __syncthreads();
    if (!isLast) return;

    // ---- merge (last CTA): stage 1200 keys, redux tournament top-15 ----
    const size_t bb = (size_t)b * NCLS * MAXO;
    for (int i = tid; i < NOKEYS; i += NTHREADS) allkeys[i] = g_keys[bb + MAXO + i];
    __syncthreads();

    if (tid < 32) {
        const int l0 = lane, l1 = lane + 32, l2 = lane + 64;
        u64 h0 = allkeys[l0 * MAXO];
        u64 h1 = allkeys[l1 * MAXO];
        u64 h2 = (lane < 16) ? allkeys[l2 * MAXO] : 0ull;
        int p0 = 0, p1 = 0, p2 = 0;

        u64 wkey = 0;
        for (int r = 0; r < MAXO; r++) {
            u64 lmax = max(h0, max(h1, h2));
            unsigned hi = (unsigned)(lmax >> 32);
            unsigned mh = __reduce_max_sync(FULL, hi);
            unsigned lo = (hi == mh) ? (unsigned)lmax : 0u;
            unsigned ml = __reduce_max_sync(FULL, lo);
            u64 win = ((u64)mh << 32) | ml;
            if (win == 0ull) break;
            if (lane == r) wkey = win;
            if (h0 == win)      { p0++; h0 = (p0 < MAXO) ? allkeys[l0 * MAXO + p0] : 0ull; }
            else if (h1 == win) { p1++; h1 = (p1 < MAXO) ? allkeys[l1 * MAXO + p1] : 0ull; }
            else if (h2 == win) { p2++; h2 = (p2 < MAXO) ? allkeys[l2 * MAXO + p2] : 0ull; }
        }

        if (lane < MAXO) {
            int slot = MAXH + lane;
            bool v = (wkey != 0ull);
            float4 wb = v ? bx4[(int)((wkey >> 8) & 0xFFFFFFull)]
                          : make_float4(0, 0, 0, 0);
            float* ob = outBoxes + ((size_t)b * KOUT + slot) * 4;
            *(float4*)ob = wb;
            outScores[b * KOUT + slot] = v ? __uint_as_float((unsigned)(wkey >> 32)) : 0.0f;
            outLabels[b * KOUT + slot] = v ? (float)(int)(wkey & 0xFFull) : -1.0f;
            outValid [b * KOUT + slot] = v ? 1.0f : 0.0f;
        }
    }
}

extern "C" void kernel_launch(void* const* d_in, const int* in_sizes, int n_in,
                              void* d_out, int out_size)
{
    const float* boxes  = (const float*)d_in[0];
    const float* scores = (const float*)d_in[1];
    const int*   labels = (const int*)d_in[2];

    int B = out_size / (KOUT * 7);        // 32
    if (B <= 0) B = 1;
    if (B > BMAX) B = BMAX;
    int N = in_sizes[1] / B;              // 2048

    dim3 grid(G, B);
    fused_kernel<<<grid, NTHREADS>>>(boxes, scores, labels, (float*)d_out, B, N);
}